// round 10
// baseline (speedup 1.0000x reference)
#include <cuda_runtime.h>
#include <cuda_bf16.h>
#include <math.h>

#define BATCH 4
#define SEQ   4096
#define EMB   512

__device__ float g_s[(size_t)BATCH * SEQ * SEQ];
__device__ __nv_bfloat16 g_qh[BATCH * SEQ * EMB], g_ql[BATCH * SEQ * EMB];
__device__ __nv_bfloat16 g_kh[BATCH * SEQ * EMB], g_kl[BATCH * SEQ * EMB];
__device__ __nv_bfloat16 g_vth[BATCH * SEQ * EMB], g_vtl[BATCH * SEQ * EMB];
__device__ __nv_bfloat16 g_ph[(size_t)BATCH * SEQ * SEQ];
__device__ __nv_bfloat16 g_pl[(size_t)BATCH * SEQ * SEQ];

__device__ __forceinline__ unsigned packbf(__nv_bfloat16 a, __nv_bfloat16 b) {
    return ((unsigned)__bfloat16_as_ushort(b) << 16) | __bfloat16_as_ushort(a);
}
__device__ __forceinline__ void split2(float x, float y, unsigned& h, unsigned& l) {
    __nv_bfloat16 hx = __float2bfloat16_rn(x);
    __nv_bfloat16 hy = __float2bfloat16_rn(y);
    __nv_bfloat16 lx = __float2bfloat16_rn(x - __bfloat162float(hx));
    __nv_bfloat16 ly = __float2bfloat16_rn(y - __bfloat162float(hy));
    h = packbf(hx, hy);
    l = packbf(lx, ly);
}
__device__ __forceinline__ void cp16(unsigned dst, const void* src) {
    asm volatile("cp.async.cg.shared.global [%0], [%1], 16;" :: "r"(dst), "l"(src));
}

// acc-target and B-fragment indices passed separately
#define MMABF2(aa, bb, mi, aj, bj)                                            \
    asm volatile(                                                             \
        "mma.sync.aligned.m16n8k16.row.col.f32.bf16.bf16.f32 "                \
        "{%0,%1,%2,%3}, {%4,%5,%6,%7}, {%8,%9}, {%0,%1,%2,%3};"               \
        : "+f"(acc[mi][aj][0]), "+f"(acc[mi][aj][1]),                         \
          "+f"(acc[mi][aj][2]), "+f"(acc[mi][aj][3])                          \
        : "r"(aa[mi][0]), "r"(aa[mi][1]), "r"(aa[mi][2]), "r"(aa[mi][3]),     \
          "r"(bb[bj][0]), "r"(bb[bj][1]))

// ===========================================================================
// Pre-split bf16 GEMM: C[m,n] = sum_k (Ah+Al)[m,k]*(Bh+Bl)[n,k], fp32 out
// CTA tile 128x256, BK=64, 512 threads (16 warps 4m x 4n), warp tile 32x64.
// ===========================================================================
#define GTILE_A 18432
#define GTILE_B 36864
#define GOFF_AH 0
#define GOFF_BH GTILE_A
#define GOFF_AL (GTILE_A + GTILE_B)
#define GOFF_BL (2 * GTILE_A + GTILE_B)
#define GSTAGE  (2 * GTILE_A + 2 * GTILE_B)
#define GSMEM   (2 * GSTAGE)                 // 221184 B

__global__ void __launch_bounds__(512)
gemm_bf16_nt(const __nv_bfloat16* __restrict__ Ah, const __nv_bfloat16* __restrict__ Al,
             const __nv_bfloat16* __restrict__ Bh, const __nv_bfloat16* __restrict__ Bl,
             float* __restrict__ C, int K, int lda, int ldb, int ldc,
             long sA, long sB, long sC)
{
    extern __shared__ unsigned su[];

    const int bz = blockIdx.z;
    Ah += (long)bz * sA; Al += (long)bz * sA;
    Bh += (long)bz * sB; Bl += (long)bz * sB;
    C  += (long)bz * sC;

    const int tid  = threadIdx.x;
    const int lane = tid & 31;
    const int wid  = tid >> 5;
    const int wm   = (wid & 3) * 32;
    const int wn   = (wid >> 2) * 64;
    const int m0   = blockIdx.y * 128;
    const int n0   = blockIdx.x * 256;

    unsigned smemU;
    asm("{ .reg .u64 t; cvta.to.shared.u64 t, %1; cvt.u32.u64 %0, t; }"
        : "=r"(smemU) : "l"(su));

    const int arow = tid >> 2;
    const int ach  = (tid & 3) * 2;
    const int brow = tid >> 1;
    const int bch  = (tid & 1) * 4;

    auto stageCopy = [&](int buf, int kt) {
        const unsigned base = smemU + (unsigned)buf * GSTAGE;
        const long ao = (long)(m0 + arow) * lda + (long)kt * 64;
        const long bo = (long)(n0 + brow) * ldb + (long)kt * 64;
#pragma unroll
        for (int i = 0; i < 2; i++) {
            const int ch = ach + i;
            const unsigned d = (unsigned)(arow * 144 + ch * 16);
            cp16(base + GOFF_AH + d, Ah + ao + ch * 8);
            cp16(base + GOFF_AL + d, Al + ao + ch * 8);
        }
#pragma unroll
        for (int i = 0; i < 4; i++) {
            const int ch = bch + i;
            const unsigned d = (unsigned)(brow * 144 + ch * 16);
            cp16(base + GOFF_BH + d, Bh + bo + ch * 8);
            cp16(base + GOFF_BL + d, Bl + bo + ch * 8);
        }
    };

    float acc[2][8][4];
#pragma unroll
    for (int i = 0; i < 2; i++)
#pragma unroll
        for (int j = 0; j < 8; j++)
#pragma unroll
            for (int r = 0; r < 4; r++) acc[i][j][r] = 0.f;

    const int r8 = lane & 7;
    const int hb = (lane >> 3) & 1;
    const int hf = lane >> 4;
    unsigned aOff[2], bOff[4];
#pragma unroll
    for (int mi = 0; mi < 2; mi++)
        aOff[mi] = ((wm + mi * 16 + r8 + hb * 8) * 72 + hf * 8) * 2;
#pragma unroll
    for (int p = 0; p < 4; p++)
        bOff[p] = ((wn + p * 16 + r8 + hf * 8) * 72) * 2 + hb * 16;

    const int niter = K >> 6;

    stageCopy(0, 0);
    asm volatile("cp.async.commit_group;");

    for (int it = 0; it < niter; it++) {
        if (it + 1 < niter) {
            stageCopy((it + 1) & 1, it + 1);
            asm volatile("cp.async.commit_group;");
            asm volatile("cp.async.wait_group 1;");
        } else {
            asm volatile("cp.async.wait_group 0;");
        }
        __syncthreads();

        const unsigned stB = smemU + (unsigned)((it & 1) * GSTAGE);
        const unsigned aH = stB + GOFF_AH;
        const unsigned bH = stB + GOFF_BH;
        const unsigned aL = stB + GOFF_AL;
        const unsigned bL = stB + GOFF_BL;

#pragma unroll
        for (int ks = 0; ks < 4; ks++) {
            unsigned aFh[2][4], aFl[2][4];
#pragma unroll
            for (int mi = 0; mi < 2; mi++) {
                asm volatile("ldmatrix.sync.aligned.m8n8.x4.shared.b16 {%0,%1,%2,%3}, [%4];"
                    : "=r"(aFh[mi][0]), "=r"(aFh[mi][1]), "=r"(aFh[mi][2]), "=r"(aFh[mi][3])
                    : "r"(aH + aOff[mi] + ks * 32));
                asm volatile("ldmatrix.sync.aligned.m8n8.x4.shared.b16 {%0,%1,%2,%3}, [%4];"
                    : "=r"(aFl[mi][0]), "=r"(aFl[mi][1]), "=r"(aFl[mi][2]), "=r"(aFl[mi][3])
                    : "r"(aL + aOff[mi] + ks * 32));
            }
#pragma unroll
            for (int p = 0; p < 4; p++) {
                unsigned bFh[2][2], bFl[2][2];
                unsigned q0, q1, q2, q3;
                asm volatile("ldmatrix.sync.aligned.m8n8.x4.shared.b16 {%0,%1,%2,%3}, [%4];"
                    : "=r"(q0), "=r"(q1), "=r"(q2), "=r"(q3)
                    : "r"(bH + bOff[p] + ks * 32));
                bFh[0][0] = q0; bFh[0][1] = q1; bFh[1][0] = q2; bFh[1][1] = q3;
                asm volatile("ldmatrix.sync.aligned.m8n8.x4.shared.b16 {%0,%1,%2,%3}, [%4];"
                    : "=r"(q0), "=r"(q1), "=r"(q2), "=r"(q3)
                    : "r"(bL + bOff[p] + ks * 32));
                bFl[0][0] = q0; bFl[0][1] = q1; bFl[1][0] = q2; bFl[1][1] = q3;
#pragma unroll
                for (int mi = 0; mi < 2; mi++)
#pragma unroll
                    for (int jj = 0; jj < 2; jj++) {
                        const int nj = p * 2 + jj;
                        MMABF2(aFh, bFl, mi, nj, jj);
                        MMABF2(aFl, bFh, mi, nj, jj);
                        MMABF2(aFh, bFh, mi, nj, jj);
                    }
            }
        }
        __syncthreads();
    }

    const int g = lane >> 2;
    const int t = lane & 3;
#pragma unroll
    for (int nj = 0; nj < 8; nj++) {
        const int col = n0 + wn + nj * 8 + t * 2;
#pragma unroll
        for (int mi = 0; mi < 2; mi++) {
            const int row = m0 + wm + mi * 16 + g;
            *reinterpret_cast<float2*>(&C[(long)row * ldc + col]) =
                make_float2(acc[mi][nj][0], acc[mi][nj][1]);
            *reinterpret_cast<float2*>(&C[(long)(row + 8) * ldc + col]) =
                make_float2(acc[mi][nj][2], acc[mi][nj][3]);
        }
    }
}

// ===========================================================================
// Projection GEMM (fp32 in, split-bf16 out): C = A @ B^T + bias  (round-8)
// ===========================================================================
#define PTILE_U  2560
#define PSTAGE_U (4 * PTILE_U)
#define PSMEM    (2 * PSTAGE_U * 4)

template <bool TRANSC>
__global__ void __launch_bounds__(512)
proj_gemm(const float* __restrict__ A, const float* __restrict__ B,
          const float* __restrict__ bias,
          __nv_bfloat16* __restrict__ Ch, __nv_bfloat16* __restrict__ Cl,
          int K, int lda, int ldb, int ldc)
{
    extern __shared__ unsigned su[];

    const int tid  = threadIdx.x;
    const int lane = tid & 31;
    const int wid  = tid >> 5;
    const int wm   = (wid & 3) * 32;
    const int wn   = (wid >> 2) * 32;
    const int m0   = blockIdx.y * 128;
    const int n0   = blockIdx.x * 128;

    const int r0c = tid >> 3;
    const int r1c = r0c + 64;
    const int k4  = (tid & 7) * 4;
    const float* Ag0 = A + (long)(m0 + r0c) * lda + k4;
    const float* Ag1 = A + (long)(m0 + r1c) * lda + k4;
    const float* Bg0 = B + (long)(n0 + r0c) * ldb + k4;
    const float* Bg1 = B + (long)(n0 + r1c) * ldb + k4;

    float acc[2][4][4];
#pragma unroll
    for (int i = 0; i < 2; i++)
#pragma unroll
        for (int j = 0; j < 4; j++)
#pragma unroll
            for (int r = 0; r < 4; r++) acc[i][j][r] = 0.f;

    unsigned smemU;
    asm("{ .reg .u64 t; cvta.to.shared.u64 t, %1; cvt.u32.u64 %0, t; }"
        : "=r"(smemU) : "l"(su));
    const int r8 = lane & 7;
    const int hb = (lane >> 3) & 1;
    const int hf = lane >> 4;
    unsigned aOff[2], bOff[2];
#pragma unroll
    for (int mi = 0; mi < 2; mi++)
        aOff[mi] = ((wm + mi * 16 + r8 + hb * 8) * 40 + hf * 8) * 2;
#pragma unroll
    for (int p = 0; p < 2; p++)
        bOff[p] = ((wn + p * 16 + r8 + hf * 8) * 40) * 2 + hb * 16;

    const int niter = K >> 5;
    const int s0 = r0c * 20 + (tid & 7) * 2;
    const int s1 = r1c * 20 + (tid & 7) * 2;

    auto splitStore = [&](int buf, float4 va0, float4 va1, float4 vb0, float4 vb1) {
        unsigned* AsH = su + buf * PSTAGE_U;
        unsigned* BsH = AsH + PTILE_U;
        unsigned* AsL = AsH + 2 * PTILE_U;
        unsigned* BsL = AsH + 3 * PTILE_U;
        unsigned h0, h1, l0, l1;
        split2(va0.x, va0.y, h0, l0); split2(va0.z, va0.w, h1, l1);
        *reinterpret_cast<uint2*>(&AsH[s0]) = make_uint2(h0, h1);
        *reinterpret_cast<uint2*>(&AsL[s0]) = make_uint2(l0, l1);
        split2(va1.x, va1.y, h0, l0); split2(va1.z, va1.w, h1, l1);
        *reinterpret_cast<uint2*>(&AsH[s1]) = make_uint2(h0, h1);
        *reinterpret_cast<uint2*>(&AsL[s1]) = make_uint2(l0, l1);
        split2(vb0.x, vb0.y, h0, l0); split2(vb0.z, vb0.w, h1, l1);
        *reinterpret_cast<uint2*>(&BsH[s0]) = make_uint2(h0, h1);
        *reinterpret_cast<uint2*>(&BsL[s0]) = make_uint2(l0, l1);
        split2(vb1.x, vb1.y, h0, l0); split2(vb1.z, vb1.w, h1, l1);
        *reinterpret_cast<uint2*>(&BsH[s1]) = make_uint2(h0, h1);
        *reinterpret_cast<uint2*>(&BsL[s1]) = make_uint2(l0, l1);
    };

    {
        float4 a0 = *reinterpret_cast<const float4*>(Ag0);
        float4 a1 = *reinterpret_cast<const float4*>(Ag1);
        float4 b0 = *reinterpret_cast<const float4*>(Bg0);
        float4 b1 = *reinterpret_cast<const float4*>(Bg1);
        splitStore(0, a0, a1, b0, b1);
    }
    __syncthreads();

    for (int it = 0; it < niter; it++) {
        const int cur = it & 1;
        float4 pa0, pa1, pb0, pb1;
        const bool more = (it + 1 < niter);
        if (more) {
            const int ko = (it + 1) * 32;
            pa0 = *reinterpret_cast<const float4*>(Ag0 + ko);
            pa1 = *reinterpret_cast<const float4*>(Ag1 + ko);
            pb0 = *reinterpret_cast<const float4*>(Bg0 + ko);
            pb1 = *reinterpret_cast<const float4*>(Bg1 + ko);
        }

        const unsigned stB = smemU + (unsigned)(cur * PSTAGE_U) * 4u;
        const unsigned aH = stB;
        const unsigned bH = stB + PTILE_U * 4u;
        const unsigned aL = stB + 2u * PTILE_U * 4u;
        const unsigned bL = stB + 3u * PTILE_U * 4u;

#pragma unroll
        for (int ks = 0; ks < 2; ks++) {
            unsigned aFh[2][4], aFl[2][4];
            unsigned bFh[4][2], bFl[4][2];
#pragma unroll
            for (int mi = 0; mi < 2; mi++) {
                asm volatile("ldmatrix.sync.aligned.m8n8.x4.shared.b16 {%0,%1,%2,%3}, [%4];"
                    : "=r"(aFh[mi][0]), "=r"(aFh[mi][1]), "=r"(aFh[mi][2]), "=r"(aFh[mi][3])
                    : "r"(aH + aOff[mi] + ks * 32));
                asm volatile("ldmatrix.sync.aligned.m8n8.x4.shared.b16 {%0,%1,%2,%3}, [%4];"
                    : "=r"(aFl[mi][0]), "=r"(aFl[mi][1]), "=r"(aFl[mi][2]), "=r"(aFl[mi][3])
                    : "r"(aL + aOff[mi] + ks * 32));
            }
#pragma unroll
            for (int p = 0; p < 2; p++) {
                unsigned q0, q1, q2, q3;
                asm volatile("ldmatrix.sync.aligned.m8n8.x4.shared.b16 {%0,%1,%2,%3}, [%4];"
                    : "=r"(q0), "=r"(q1), "=r"(q2), "=r"(q3)
                    : "r"(bH + bOff[p] + ks * 32));
                bFh[2 * p][0] = q0; bFh[2 * p][1] = q1;
                bFh[2 * p + 1][0] = q2; bFh[2 * p + 1][1] = q3;
                asm volatile("ldmatrix.sync.aligned.m8n8.x4.shared.b16 {%0,%1,%2,%3}, [%4];"
                    : "=r"(q0), "=r"(q1), "=r"(q2), "=r"(q3)
                    : "r"(bL + bOff[p] + ks * 32));
                bFl[2 * p][0] = q0; bFl[2 * p][1] = q1;
                bFl[2 * p + 1][0] = q2; bFl[2 * p + 1][1] = q3;
            }
#pragma unroll
            for (int mi = 0; mi < 2; mi++)
#pragma unroll
                for (int nj = 0; nj < 4; nj++) {
                    MMABF2(aFh, bFl, mi, nj, nj);
                    MMABF2(aFl, bFh, mi, nj, nj);
                    MMABF2(aFh, bFh, mi, nj, nj);
                }
        }

        if (more) splitStore(1 - cur, pa0, pa1, pb0, pb1);
        __syncthreads();
    }

    const int g = lane >> 2;
    const int t = lane & 3;
#pragma unroll
    for (int nj = 0; nj < 4; nj++) {
        const int col = n0 + wn + nj * 8 + t * 2;
        const float b0 = bias[col];
        const float b1 = bias[col + 1];
#pragma unroll
        for (int mi = 0; mi < 2; mi++) {
            const int row = m0 + wm + mi * 16 + g;
            float c[4] = {acc[mi][nj][0] + b0, acc[mi][nj][1] + b1,
                          acc[mi][nj][2] + b0, acc[mi][nj][3] + b1};
            __nv_bfloat16 h[4], l[4];
#pragma unroll
            for (int q = 0; q < 4; q++) {
                h[q] = __float2bfloat16_rn(c[q]);
                l[q] = __float2bfloat16_rn(c[q] - __bfloat162float(h[q]));
            }
            if (!TRANSC) {
                *reinterpret_cast<unsigned*>(&Ch[(long)row * ldc + col])       = packbf(h[0], h[1]);
                *reinterpret_cast<unsigned*>(&Cl[(long)row * ldc + col])       = packbf(l[0], l[1]);
                *reinterpret_cast<unsigned*>(&Ch[(long)(row + 8) * ldc + col]) = packbf(h[2], h[3]);
                *reinterpret_cast<unsigned*>(&Cl[(long)(row + 8) * ldc + col]) = packbf(l[2], l[3]);
            } else {
                const int bb = row >> 12;
                const int s  = row & 4095;
                __nv_bfloat16* Cbh = Ch + (long)bb * EMB * SEQ + s;
                __nv_bfloat16* Cbl = Cl + (long)bb * EMB * SEQ + s;
                Cbh[(long)col * SEQ]           = h[0];
                Cbh[(long)(col + 1) * SEQ]     = h[1];
                Cbh[(long)col * SEQ + 8]       = h[2];
                Cbh[(long)(col + 1) * SEQ + 8] = h[3];
                Cbl[(long)col * SEQ]           = l[0];
                Cbl[(long)(col + 1) * SEQ]     = l[1];
                Cbl[(long)col * SEQ + 8]       = l[2];
                Cbl[(long)(col + 1) * SEQ + 8] = l[3];
            }
        }
    }
}

// ---------------------------------------------------------------------------
// Row softmax: read fp32 scores, write split-bf16 attn. 256 thr / 4096 cols.
// ---------------------------------------------------------------------------
__global__ void __launch_bounds__(256)
softmax_split(const float* __restrict__ S,
              __nv_bfloat16* __restrict__ Ph, __nv_bfloat16* __restrict__ Pl)
{
    const long row = blockIdx.x;
    const float* p = S + row * (long)SEQ;
    const int tid  = threadIdx.x;
    const int lane = tid & 31;
    const int wid  = tid >> 5;

    float vals[16];
    float m = -3.0e38f;
#pragma unroll
    for (int i = 0; i < 4; i++) {
        float4 v = reinterpret_cast<const float4*>(p)[tid + i * 256];
        vals[i * 4 + 0] = v.x; vals[i * 4 + 1] = v.y;
        vals[i * 4 + 2] = v.z; vals[i * 4 + 3] = v.w;
        m = fmaxf(m, fmaxf(fmaxf(v.x, v.y), fmaxf(v.z, v.w)));
    }

    __shared__ float red[8];
#pragma unroll
    for (int off = 16; off > 0; off >>= 1)
        m = fmaxf(m, __shfl_xor_sync(0xffffffffu, m, off));
    if (lane == 0) red[wid] = m;
    __syncthreads();
    float mAll = red[0];
#pragma unroll
    for (int w = 1; w < 8; w++) mAll = fmaxf(mAll, red[w]);
    __syncthreads();

    float s = 0.f;
#pragma unroll
    for (int i = 0; i < 16; i++) {
        vals[i] = __expf(vals[i] - mAll);
        s += vals[i];
    }
#pragma unroll
    for (int off = 16; off > 0; off >>= 1)
        s += __shfl_xor_sync(0xffffffffu, s, off);
    if (lane == 0) red[wid] = s;
    __syncthreads();
    float sAll = 0.f;
#pragma unroll
    for (int w = 0; w < 8; w++) sAll += red[w];
    const float inv = 1.0f / sAll;

    uint2* ph = reinterpret_cast<uint2*>(Ph + row * (long)SEQ);
    uint2* pl = reinterpret_cast<uint2*>(Pl + row * (long)SEQ);
#pragma unroll
    for (int i = 0; i < 4; i++) {
        unsigned h0, h1, l0, l1;
        split2(vals[i * 4 + 0] * inv, vals[i * 4 + 1] * inv, h0, l0);
        split2(vals[i * 4 + 2] * inv, vals[i * 4 + 3] * inv, h1, l1);
        ph[tid + i * 256] = make_uint2(h0, h1);
        pl[tid + i * 256] = make_uint2(l0, l1);
    }
}

// ---------------------------------------------------------------------------
extern "C" void kernel_launch(void* const* d_in, const int* in_sizes, int n_in,
                              void* d_out, int out_size)
{
    const float* q_in = (const float*)d_in[0];
    const float* k_in = (const float*)d_in[1];
    const float* v_in = (const float*)d_in[2];
    const float* Wq   = (const float*)d_in[3];
    const float* bq   = (const float*)d_in[4];
    const float* Wk   = (const float*)d_in[5];
    const float* bk   = (const float*)d_in[6];
    const float* Wv   = (const float*)d_in[7];
    const float* bv   = (const float*)d_in[8];
    float* out = (float*)d_out;

    float* gs;
    __nv_bfloat16 *qh, *ql, *kh, *kl, *vth, *vtl, *ph, *pl;
    cudaGetSymbolAddress((void**)&gs,  g_s);
    cudaGetSymbolAddress((void**)&qh,  g_qh);  cudaGetSymbolAddress((void**)&ql, g_ql);
    cudaGetSymbolAddress((void**)&kh,  g_kh);  cudaGetSymbolAddress((void**)&kl, g_kl);
    cudaGetSymbolAddress((void**)&vth, g_vth); cudaGetSymbolAddress((void**)&vtl, g_vtl);
    cudaGetSymbolAddress((void**)&ph,  g_ph);  cudaGetSymbolAddress((void**)&pl, g_pl);

    static bool attrDone = false;
    if (!attrDone) {
        cudaFuncSetAttribute(proj_gemm<false>,
                             cudaFuncAttributeMaxDynamicSharedMemorySize, PSMEM);
        cudaFuncSetAttribute(proj_gemm<true>,
                             cudaFuncAttributeMaxDynamicSharedMemorySize, PSMEM);
        cudaFuncSetAttribute(gemm_bf16_nt,
                             cudaFuncAttributeMaxDynamicSharedMemorySize, GSMEM);
        attrDone = true;
    }

    // 1) projections -> split bf16 (V transposed)
    {
        dim3 grd(EMB / 128, (BATCH * SEQ) / 128, 1);
        proj_gemm<false><<<grd, 512, PSMEM>>>(q_in, Wq, bq, qh, ql, EMB, EMB, EMB, EMB);
        proj_gemm<false><<<grd, 512, PSMEM>>>(k_in, Wk, bk, kh, kl, EMB, EMB, EMB, EMB);
        proj_gemm<true><<<grd, 512, PSMEM>>>(v_in, Wv, bv, vth, vtl, EMB, EMB, EMB, SEQ);
    }

    // 2) scores[b] = q[b] @ k[b]^T  (CTA 128x256)
    {
        dim3 grd(SEQ / 256, SEQ / 128, BATCH);
        gemm_bf16_nt<<<grd, 512, GSMEM>>>(qh, ql, kh, kl, gs, EMB, EMB, EMB, SEQ,
                                          (long)SEQ * EMB, (long)SEQ * EMB,
                                          (long)SEQ * SEQ);
    }

    // 3) softmax -> split bf16 attn
    softmax_split<<<BATCH * SEQ, 256>>>(gs, ph, pl);

    // 4) out[b] = attn[b] @ v[b]
    {
        dim3 grd(EMB / 256, SEQ / 128, BATCH);
        gemm_bf16_nt<<<grd, 512, GSMEM>>>(ph, pl, vth, vtl, out, SEQ, SEQ, SEQ, EMB,
                                          (long)SEQ * SEQ, (long)EMB * SEQ,
                                          (long)SEQ * EMB);
    }
}

// round 11
// speedup vs baseline: 1.3819x; 1.3819x over previous
#include <cuda_runtime.h>
#include <cuda_fp16.h>
#include <math.h>

#define BATCH 4
#define SEQ   4096
#define EMB   512

// Scratch (__device__ globals: sanctioned, no runtime allocation)
__device__ float g_s[(size_t)BATCH * SEQ * SEQ];                  // 256 MB scores
__device__ __half g_qh[BATCH * SEQ * EMB], g_ql[BATCH * SEQ * EMB];
__device__ __half g_kh[BATCH * SEQ * EMB], g_kl[BATCH * SEQ * EMB];
__device__ __half g_vt[BATCH * SEQ * EMB];                        // [b][e][s] single
__device__ __half g_p [(size_t)BATCH * SEQ * SEQ];                // 128 MB attn single

__device__ __forceinline__ unsigned packh(__half a, __half b) {
    return ((unsigned)__half_as_ushort(b) << 16) | __half_as_ushort(a);
}
__device__ __forceinline__ void split2h(float x, float y, unsigned& h, unsigned& l) {
    __half hx = __float2half_rn(x);
    __half hy = __float2half_rn(y);
    __half lx = __float2half_rn(x - __half2float(hx));
    __half ly = __float2half_rn(y - __half2float(hy));
    h = packh(hx, hy);
    l = packh(lx, ly);
}
__device__ __forceinline__ void cp16(unsigned dst, const void* src) {
    asm volatile("cp.async.cg.shared.global [%0], [%1], 16;" :: "r"(dst), "l"(src));
}

// acc target index and B-fragment index passed separately
#define MMAH(aa, bb, mi, aj, bj)                                              \
    asm volatile(                                                             \
        "mma.sync.aligned.m16n8k16.row.col.f32.f16.f16.f32 "                  \
        "{%0,%1,%2,%3}, {%4,%5,%6,%7}, {%8,%9}, {%0,%1,%2,%3};"               \
        : "+f"(acc[mi][aj][0]), "+f"(acc[mi][aj][1]),                         \
          "+f"(acc[mi][aj][2]), "+f"(acc[mi][aj][3])                          \
        : "r"(aa[mi][0]), "r"(aa[mi][1]), "r"(aa[mi][2]), "r"(aa[mi][3]),     \
          "r"(bb[bj][0]), "r"(bb[bj][1]))

// ===========================================================================
// Projection GEMM (fp32 in, split-fp16 out): C = A @ B^T + bias
// Validated round-8 structure: 128x128 tile, BK=32, 512 thr, split at staging.
// WRITE_LO=false: only hi written (V path). TRANSC: scatter into [b][e][s].
// ===========================================================================
#define PTILE_U  2560                        // u32 per tile (128 rows * 20)
#define PSTAGE_U (4 * PTILE_U)
#define PSMEM    (2 * PSTAGE_U * 4)          // 81920 B

template <bool TRANSC, bool WRITE_LO>
__global__ void __launch_bounds__(512)
proj_gemm(const float* __restrict__ A, const float* __restrict__ B,
          const float* __restrict__ bias,
          __half* __restrict__ Ch, __half* __restrict__ Cl,
          int K, int lda, int ldb, int ldc)
{
    extern __shared__ unsigned su[];

    const int tid  = threadIdx.x;
    const int lane = tid & 31;
    const int wid  = tid >> 5;
    const int wm   = (wid & 3) * 32;
    const int wn   = (wid >> 2) * 32;
    const int m0   = blockIdx.y * 128;
    const int n0   = blockIdx.x * 128;

    const int r0c = tid >> 3;
    const int r1c = r0c + 64;
    const int k4  = (tid & 7) * 4;
    const float* Ag0 = A + (long)(m0 + r0c) * lda + k4;
    const float* Ag1 = A + (long)(m0 + r1c) * lda + k4;
    const float* Bg0 = B + (long)(n0 + r0c) * ldb + k4;
    const float* Bg1 = B + (long)(n0 + r1c) * ldb + k4;

    float acc[2][4][4];
#pragma unroll
    for (int i = 0; i < 2; i++)
#pragma unroll
        for (int j = 0; j < 4; j++)
#pragma unroll
            for (int r = 0; r < 4; r++) acc[i][j][r] = 0.f;

    unsigned smemU;
    asm("{ .reg .u64 t; cvta.to.shared.u64 t, %1; cvt.u32.u64 %0, t; }"
        : "=r"(smemU) : "l"(su));
    const int r8 = lane & 7;
    const int hb = (lane >> 3) & 1;
    const int hf = lane >> 4;
    unsigned aOff[2], bOff[2];
#pragma unroll
    for (int mi = 0; mi < 2; mi++)
        aOff[mi] = ((wm + mi * 16 + r8 + hb * 8) * 40 + hf * 8) * 2;
#pragma unroll
    for (int p = 0; p < 2; p++)
        bOff[p] = ((wn + p * 16 + r8 + hf * 8) * 40) * 2 + hb * 16;

    const int niter = K >> 5;
    const int s0 = r0c * 20 + (tid & 7) * 2;
    const int s1 = r1c * 20 + (tid & 7) * 2;

    auto splitStore = [&](int buf, float4 va0, float4 va1, float4 vb0, float4 vb1) {
        unsigned* AsH = su + buf * PSTAGE_U;
        unsigned* BsH = AsH + PTILE_U;
        unsigned* AsL = AsH + 2 * PTILE_U;
        unsigned* BsL = AsH + 3 * PTILE_U;
        unsigned h0, h1, l0, l1;
        split2h(va0.x, va0.y, h0, l0); split2h(va0.z, va0.w, h1, l1);
        *reinterpret_cast<uint2*>(&AsH[s0]) = make_uint2(h0, h1);
        *reinterpret_cast<uint2*>(&AsL[s0]) = make_uint2(l0, l1);
        split2h(va1.x, va1.y, h0, l0); split2h(va1.z, va1.w, h1, l1);
        *reinterpret_cast<uint2*>(&AsH[s1]) = make_uint2(h0, h1);
        *reinterpret_cast<uint2*>(&AsL[s1]) = make_uint2(l0, l1);
        split2h(vb0.x, vb0.y, h0, l0); split2h(vb0.z, vb0.w, h1, l1);
        *reinterpret_cast<uint2*>(&BsH[s0]) = make_uint2(h0, h1);
        *reinterpret_cast<uint2*>(&BsL[s0]) = make_uint2(l0, l1);
        split2h(vb1.x, vb1.y, h0, l0); split2h(vb1.z, vb1.w, h1, l1);
        *reinterpret_cast<uint2*>(&BsH[s1]) = make_uint2(h0, h1);
        *reinterpret_cast<uint2*>(&BsL[s1]) = make_uint2(l0, l1);
    };

    {
        float4 a0 = *reinterpret_cast<const float4*>(Ag0);
        float4 a1 = *reinterpret_cast<const float4*>(Ag1);
        float4 b0 = *reinterpret_cast<const float4*>(Bg0);
        float4 b1 = *reinterpret_cast<const float4*>(Bg1);
        splitStore(0, a0, a1, b0, b1);
    }
    __syncthreads();

    for (int it = 0; it < niter; it++) {
        const int cur = it & 1;
        float4 pa0, pa1, pb0, pb1;
        const bool more = (it + 1 < niter);
        if (more) {
            const int ko = (it + 1) * 32;
            pa0 = *reinterpret_cast<const float4*>(Ag0 + ko);
            pa1 = *reinterpret_cast<const float4*>(Ag1 + ko);
            pb0 = *reinterpret_cast<const float4*>(Bg0 + ko);
            pb1 = *reinterpret_cast<const float4*>(Bg1 + ko);
        }

        const unsigned stB = smemU + (unsigned)(cur * PSTAGE_U) * 4u;
        const unsigned aH = stB;
        const unsigned bH = stB + PTILE_U * 4u;
        const unsigned aL = stB + 2u * PTILE_U * 4u;
        const unsigned bL = stB + 3u * PTILE_U * 4u;

#pragma unroll
        for (int ks = 0; ks < 2; ks++) {
            unsigned aFh[2][4], aFl[2][4];
            unsigned bFh[4][2], bFl[4][2];
#pragma unroll
            for (int mi = 0; mi < 2; mi++) {
                asm volatile("ldmatrix.sync.aligned.m8n8.x4.shared.b16 {%0,%1,%2,%3}, [%4];"
                    : "=r"(aFh[mi][0]), "=r"(aFh[mi][1]), "=r"(aFh[mi][2]), "=r"(aFh[mi][3])
                    : "r"(aH + aOff[mi] + ks * 32));
                asm volatile("ldmatrix.sync.aligned.m8n8.x4.shared.b16 {%0,%1,%2,%3}, [%4];"
                    : "=r"(aFl[mi][0]), "=r"(aFl[mi][1]), "=r"(aFl[mi][2]), "=r"(aFl[mi][3])
                    : "r"(aL + aOff[mi] + ks * 32));
            }
#pragma unroll
            for (int p = 0; p < 2; p++) {
                unsigned q0, q1, q2, q3;
                asm volatile("ldmatrix.sync.aligned.m8n8.x4.shared.b16 {%0,%1,%2,%3}, [%4];"
                    : "=r"(q0), "=r"(q1), "=r"(q2), "=r"(q3)
                    : "r"(bH + bOff[p] + ks * 32));
                bFh[2 * p][0] = q0; bFh[2 * p][1] = q1;
                bFh[2 * p + 1][0] = q2; bFh[2 * p + 1][1] = q3;
                asm volatile("ldmatrix.sync.aligned.m8n8.x4.shared.b16 {%0,%1,%2,%3}, [%4];"
                    : "=r"(q0), "=r"(q1), "=r"(q2), "=r"(q3)
                    : "r"(bL + bOff[p] + ks * 32));
                bFl[2 * p][0] = q0; bFl[2 * p][1] = q1;
                bFl[2 * p + 1][0] = q2; bFl[2 * p + 1][1] = q3;
            }
#pragma unroll
            for (int mi = 0; mi < 2; mi++)
#pragma unroll
                for (int nj = 0; nj < 4; nj++) {
                    MMAH(aFh, bFl, mi, nj, nj);
                    MMAH(aFl, bFh, mi, nj, nj);
                    MMAH(aFh, bFh, mi, nj, nj);
                }
        }

        if (more) splitStore(1 - cur, pa0, pa1, pb0, pb1);
        __syncthreads();
    }

    const int g = lane >> 2;
    const int t = lane & 3;
#pragma unroll
    for (int nj = 0; nj < 4; nj++) {
        const int col = n0 + wn + nj * 8 + t * 2;
        const float b0 = bias[col];
        const float b1 = bias[col + 1];
#pragma unroll
        for (int mi = 0; mi < 2; mi++) {
            const int row = m0 + wm + mi * 16 + g;
            float c[4] = {acc[mi][nj][0] + b0, acc[mi][nj][1] + b1,
                          acc[mi][nj][2] + b0, acc[mi][nj][3] + b1};
            __half h[4], l[4];
#pragma unroll
            for (int q = 0; q < 4; q++) {
                h[q] = __float2half_rn(c[q]);
                l[q] = __float2half_rn(c[q] - __half2float(h[q]));
            }
            if (!TRANSC) {
                *reinterpret_cast<unsigned*>(&Ch[(long)row * ldc + col])       = packh(h[0], h[1]);
                *reinterpret_cast<unsigned*>(&Ch[(long)(row + 8) * ldc + col]) = packh(h[2], h[3]);
                if (WRITE_LO) {
                    *reinterpret_cast<unsigned*>(&Cl[(long)row * ldc + col])       = packh(l[0], l[1]);
                    *reinterpret_cast<unsigned*>(&Cl[(long)(row + 8) * ldc + col]) = packh(l[2], l[3]);
                }
            } else {
                const int bb = row >> 12;
                const int s  = row & 4095;
                __half* Cbh = Ch + (long)bb * EMB * SEQ + s;
                Cbh[(long)col * SEQ]           = h[0];
                Cbh[(long)(col + 1) * SEQ]     = h[1];
                Cbh[(long)col * SEQ + 8]       = h[2];
                Cbh[(long)(col + 1) * SEQ + 8] = h[3];
            }
        }
    }
}

// ===========================================================================
// Score GEMM x2 (pre-split fp16 in, fp32 out): validated round-8 structure.
// CTA 128x128, BK=64, 512 threads, cp.async double buffer, 72-elem rows.
// ===========================================================================
#define GTILE_B  18432                       // 128 * 72 * 2 bytes
#define GSTAGE_B (4 * GTILE_B)
#define GSMEM    (2 * GSTAGE_B)              // 147456 B

__global__ void __launch_bounds__(512)
gemm_h2_nt(const __half* __restrict__ Ah, const __half* __restrict__ Al,
           const __half* __restrict__ Bh, const __half* __restrict__ Bl,
           float* __restrict__ C, int K, int lda, int ldb, int ldc,
           long sA, long sB, long sC)
{
    extern __shared__ unsigned su[];

    const int bz = blockIdx.z;
    Ah += (long)bz * sA; Al += (long)bz * sA;
    Bh += (long)bz * sB; Bl += (long)bz * sB;
    C  += (long)bz * sC;

    const int tid  = threadIdx.x;
    const int lane = tid & 31;
    const int wid  = tid >> 5;
    const int wm   = (wid & 3) * 32;
    const int wn   = (wid >> 2) * 32;
    const int m0   = blockIdx.y * 128;
    const int n0   = blockIdx.x * 128;

    unsigned smemU;
    asm("{ .reg .u64 t; cvta.to.shared.u64 t, %1; cvt.u32.u64 %0, t; }"
        : "=r"(smemU) : "l"(su));

    const int crow = tid >> 2;
    const int cc   = (tid & 3) * 8;
    const unsigned dsto = (unsigned)(crow * 144 + cc * 2);

    auto stageCopy = [&](int buf, int kt) {
        const unsigned base = smemU + (unsigned)buf * GSTAGE_B;
        const long ao = (long)(m0 + crow) * lda + (long)kt * 64 + cc;
        const long bo = (long)(n0 + crow) * ldb + (long)kt * 64 + cc;
        cp16(base + 0 * GTILE_B + dsto,      Ah + ao);
        cp16(base + 0 * GTILE_B + dsto + 64, Ah + ao + 32);
        cp16(base + 1 * GTILE_B + dsto,      Bh + bo);
        cp16(base + 1 * GTILE_B + dsto + 64, Bh + bo + 32);
        cp16(base + 2 * GTILE_B + dsto,      Al + ao);
        cp16(base + 2 * GTILE_B + dsto + 64, Al + ao + 32);
        cp16(base + 3 * GTILE_B + dsto,      Bl + bo);
        cp16(base + 3 * GTILE_B + dsto + 64, Bl + bo + 32);
    };

    float acc[2][4][4];
#pragma unroll
    for (int i = 0; i < 2; i++)
#pragma unroll
        for (int j = 0; j < 4; j++)
#pragma unroll
            for (int r = 0; r < 4; r++) acc[i][j][r] = 0.f;

    const int r8 = lane & 7;
    const int hb = (lane >> 3) & 1;
    const int hf = lane >> 4;
    unsigned aOff[2], bOff[2];
#pragma unroll
    for (int mi = 0; mi < 2; mi++)
        aOff[mi] = ((wm + mi * 16 + r8 + hb * 8) * 72 + hf * 8) * 2;
#pragma unroll
    for (int p = 0; p < 2; p++)
        bOff[p] = ((wn + p * 16 + r8 + hf * 8) * 72) * 2 + hb * 16;

    const int niter = K >> 6;

    stageCopy(0, 0);
    asm volatile("cp.async.commit_group;");

    for (int it = 0; it < niter; it++) {
        if (it + 1 < niter) {
            stageCopy((it + 1) & 1, it + 1);
            asm volatile("cp.async.commit_group;");
            asm volatile("cp.async.wait_group 1;");
        } else {
            asm volatile("cp.async.wait_group 0;");
        }
        __syncthreads();

        const unsigned stB = smemU + (unsigned)((it & 1) * GSTAGE_B);
        const unsigned aH = stB;
        const unsigned bH = stB + GTILE_B;
        const unsigned aL = stB + 2u * GTILE_B;
        const unsigned bL = stB + 3u * GTILE_B;

#pragma unroll
        for (int ks = 0; ks < 4; ks++) {
            unsigned aFh[2][4], aFl[2][4];
            unsigned bFh[4][2], bFl[4][2];
#pragma unroll
            for (int mi = 0; mi < 2; mi++) {
                asm volatile("ldmatrix.sync.aligned.m8n8.x4.shared.b16 {%0,%1,%2,%3}, [%4];"
                    : "=r"(aFh[mi][0]), "=r"(aFh[mi][1]), "=r"(aFh[mi][2]), "=r"(aFh[mi][3])
                    : "r"(aH + aOff[mi] + ks * 32));
                asm volatile("ldmatrix.sync.aligned.m8n8.x4.shared.b16 {%0,%1,%2,%3}, [%4];"
                    : "=r"(aFl[mi][0]), "=r"(aFl[mi][1]), "=r"(aFl[mi][2]), "=r"(aFl[mi][3])
                    : "r"(aL + aOff[mi] + ks * 32));
            }
#pragma unroll
            for (int p = 0; p < 2; p++) {
                unsigned q0, q1, q2, q3;
                asm volatile("ldmatrix.sync.aligned.m8n8.x4.shared.b16 {%0,%1,%2,%3}, [%4];"
                    : "=r"(q0), "=r"(q1), "=r"(q2), "=r"(q3)
                    : "r"(bH + bOff[p] + ks * 32));
                bFh[2 * p][0] = q0; bFh[2 * p][1] = q1;
                bFh[2 * p + 1][0] = q2; bFh[2 * p + 1][1] = q3;
                asm volatile("ldmatrix.sync.aligned.m8n8.x4.shared.b16 {%0,%1,%2,%3}, [%4];"
                    : "=r"(q0), "=r"(q1), "=r"(q2), "=r"(q3)
                    : "r"(bL + bOff[p] + ks * 32));
                bFl[2 * p][0] = q0; bFl[2 * p][1] = q1;
                bFl[2 * p + 1][0] = q2; bFl[2 * p + 1][1] = q3;
            }
#pragma unroll
            for (int mi = 0; mi < 2; mi++)
#pragma unroll
                for (int nj = 0; nj < 4; nj++) {
                    MMAH(aFh, bFl, mi, nj, nj);
                    MMAH(aFl, bFh, mi, nj, nj);
                    MMAH(aFh, bFh, mi, nj, nj);
                }
        }
        __syncthreads();
    }

    const int g = lane >> 2;
    const int t = lane & 3;
#pragma unroll
    for (int nj = 0; nj < 4; nj++) {
        const int col = n0 + wn + nj * 8 + t * 2;
#pragma unroll
        for (int mi = 0; mi < 2; mi++) {
            const int row = m0 + wm + mi * 16 + g;
            *reinterpret_cast<float2*>(&C[(long)row * ldc + col]) =
                make_float2(acc[mi][nj][0], acc[mi][nj][1]);
            *reinterpret_cast<float2*>(&C[(long)(row + 8) * ldc + col]) =
                make_float2(acc[mi][nj][2], acc[mi][nj][3]);
        }
    }
}

// ===========================================================================
// AV GEMM x1 (single fp16 in, fp32 out): C[m,n] = sum_k A[m,k]*B[n,k]
// Same structure, only hi tiles: 36 KB/stage -> 2 CTAs/SM possible.
// ===========================================================================
#define H1STAGE_B (2 * GTILE_B)              // 36864
#define H1SMEM    (2 * H1STAGE_B)            // 73728 B

__global__ void __launch_bounds__(512)
gemm_h1_nt(const __half* __restrict__ A, const __half* __restrict__ B,
           float* __restrict__ C, int K, int lda, int ldb, int ldc,
           long sA, long sB, long sC)
{
    extern __shared__ unsigned su[];

    const int bz = blockIdx.z;
    A += (long)bz * sA;
    B += (long)bz * sB;
    C += (long)bz * sC;

    const int tid  = threadIdx.x;
    const int lane = tid & 31;
    const int wid  = tid >> 5;
    const int wm   = (wid & 3) * 32;
    const int wn   = (wid >> 2) * 32;
    const int m0   = blockIdx.y * 128;
    const int n0   = blockIdx.x * 128;

    unsigned smemU;
    asm("{ .reg .u64 t; cvta.to.shared.u64 t, %1; cvt.u32.u64 %0, t; }"
        : "=r"(smemU) : "l"(su));

    const int crow = tid >> 2;
    const int cc   = (tid & 3) * 8;
    const unsigned dsto = (unsigned)(crow * 144 + cc * 2);

    auto stageCopy = [&](int buf, int kt) {
        const unsigned base = smemU + (unsigned)buf * H1STAGE_B;
        const long ao = (long)(m0 + crow) * lda + (long)kt * 64 + cc;
        const long bo = (long)(n0 + crow) * ldb + (long)kt * 64 + cc;
        cp16(base + 0 * GTILE_B + dsto,      A + ao);
        cp16(base + 0 * GTILE_B + dsto + 64, A + ao + 32);
        cp16(base + 1 * GTILE_B + dsto,      B + bo);
        cp16(base + 1 * GTILE_B + dsto + 64, B + bo + 32);
    };

    float acc[2][4][4];
#pragma unroll
    for (int i = 0; i < 2; i++)
#pragma unroll
        for (int j = 0; j < 4; j++)
#pragma unroll
            for (int r = 0; r < 4; r++) acc[i][j][r] = 0.f;

    const int r8 = lane & 7;
    const int hb = (lane >> 3) & 1;
    const int hf = lane >> 4;
    unsigned aOff[2], bOff[2];
#pragma unroll
    for (int mi = 0; mi < 2; mi++)
        aOff[mi] = ((wm + mi * 16 + r8 + hb * 8) * 72 + hf * 8) * 2;
#pragma unroll
    for (int p = 0; p < 2; p++)
        bOff[p] = ((wn + p * 16 + r8 + hf * 8) * 72) * 2 + hb * 16;

    const int niter = K >> 6;

    stageCopy(0, 0);
    asm volatile("cp.async.commit_group;");

    for (int it = 0; it < niter; it++) {
        if (it + 1 < niter) {
            stageCopy((it + 1) & 1, it + 1);
            asm volatile("cp.async.commit_group;");
            asm volatile("cp.async.wait_group 1;");
        } else {
            asm volatile("cp.async.wait_group 0;");
        }
        __syncthreads();

        const unsigned stB = smemU + (unsigned)((it & 1) * H1STAGE_B);
        const unsigned aH = stB;
        const unsigned bH = stB + GTILE_B;

#pragma unroll
        for (int ks = 0; ks < 4; ks++) {
            unsigned aF[2][4];
            unsigned bF[4][2];
#pragma unroll
            for (int mi = 0; mi < 2; mi++) {
                asm volatile("ldmatrix.sync.aligned.m8n8.x4.shared.b16 {%0,%1,%2,%3}, [%4];"
                    : "=r"(aF[mi][0]), "=r"(aF[mi][1]), "=r"(aF[mi][2]), "=r"(aF[mi][3])
                    : "r"(aH + aOff[mi] + ks * 32));
            }
#pragma unroll
            for (int p = 0; p < 2; p++) {
                unsigned q0, q1, q2, q3;
                asm volatile("ldmatrix.sync.aligned.m8n8.x4.shared.b16 {%0,%1,%2,%3}, [%4];"
                    : "=r"(q0), "=r"(q1), "=r"(q2), "=r"(q3)
                    : "r"(bH + bOff[p] + ks * 32));
                bF[2 * p][0] = q0; bF[2 * p][1] = q1;
                bF[2 * p + 1][0] = q2; bF[2 * p + 1][1] = q3;
            }
#pragma unroll
            for (int mi = 0; mi < 2; mi++)
#pragma unroll
                for (int nj = 0; nj < 4; nj++)
                    MMAH(aF, bF, mi, nj, nj);
        }
        __syncthreads();
    }

    const int g = lane >> 2;
    const int t = lane & 3;
#pragma unroll
    for (int nj = 0; nj < 4; nj++) {
        const int col = n0 + wn + nj * 8 + t * 2;
#pragma unroll
        for (int mi = 0; mi < 2; mi++) {
            const int row = m0 + wm + mi * 16 + g;
            *reinterpret_cast<float2*>(&C[(long)row * ldc + col]) =
                make_float2(acc[mi][nj][0], acc[mi][nj][1]);
            *reinterpret_cast<float2*>(&C[(long)(row + 8) * ldc + col]) =
                make_float2(acc[mi][nj][2], acc[mi][nj][3]);
        }
    }
}

// ---------------------------------------------------------------------------
// Row softmax: read fp32 scores, write single fp16 attn. 256 thr / 4096 cols.
// ---------------------------------------------------------------------------
__global__ void __launch_bounds__(256)
softmax_h(const float* __restrict__ S, __half* __restrict__ P)
{
    const long row = blockIdx.x;
    const float* p = S + row * (long)SEQ;
    const int tid  = threadIdx.x;
    const int lane = tid & 31;
    const int wid  = tid >> 5;

    float vals[16];
    float m = -3.0e38f;
#pragma unroll
    for (int i = 0; i < 4; i++) {
        float4 v = reinterpret_cast<const float4*>(p)[tid + i * 256];
        vals[i * 4 + 0] = v.x; vals[i * 4 + 1] = v.y;
        vals[i * 4 + 2] = v.z; vals[i * 4 + 3] = v.w;
        m = fmaxf(m, fmaxf(fmaxf(v.x, v.y), fmaxf(v.z, v.w)));
    }

    __shared__ float red[8];
#pragma unroll
    for (int off = 16; off > 0; off >>= 1)
        m = fmaxf(m, __shfl_xor_sync(0xffffffffu, m, off));
    if (lane == 0) red[wid] = m;
    __syncthreads();
    float mAll = red[0];
#pragma unroll
    for (int w = 1; w < 8; w++) mAll = fmaxf(mAll, red[w]);
    __syncthreads();

    float s = 0.f;
#pragma unroll
    for (int i = 0; i < 16; i++) {
        vals[i] = __expf(vals[i] - mAll);
        s += vals[i];
    }
#pragma unroll
    for (int off = 16; off > 0; off >>= 1)
        s += __shfl_xor_sync(0xffffffffu, s, off);
    if (lane == 0) red[wid] = s;
    __syncthreads();
    float sAll = 0.f;
#pragma unroll
    for (int w = 0; w < 8; w++) sAll += red[w];
    const float inv = 1.0f / sAll;

    uint2* ph = reinterpret_cast<uint2*>(P + row * (long)SEQ);
#pragma unroll
    for (int i = 0; i < 4; i++) {
        unsigned h0 = packh(__float2half_rn(vals[i * 4 + 0] * inv),
                            __float2half_rn(vals[i * 4 + 1] * inv));
        unsigned h1 = packh(__float2half_rn(vals[i * 4 + 2] * inv),
                            __float2half_rn(vals[i * 4 + 3] * inv));
        ph[tid + i * 256] = make_uint2(h0, h1);
    }
}

// ---------------------------------------------------------------------------
extern "C" void kernel_launch(void* const* d_in, const int* in_sizes, int n_in,
                              void* d_out, int out_size)
{
    const float* q_in = (const float*)d_in[0];
    const float* k_in = (const float*)d_in[1];
    const float* v_in = (const float*)d_in[2];
    const float* Wq   = (const float*)d_in[3];
    const float* bq   = (const float*)d_in[4];
    const float* Wk   = (const float*)d_in[5];
    const float* bk   = (const float*)d_in[6];
    const float* Wv   = (const float*)d_in[7];
    const float* bv   = (const float*)d_in[8];
    float* out = (float*)d_out;

    float* gs;
    __half *qh, *ql, *kh, *kl, *vt, *pp;
    cudaGetSymbolAddress((void**)&gs, g_s);
    cudaGetSymbolAddress((void**)&qh, g_qh);  cudaGetSymbolAddress((void**)&ql, g_ql);
    cudaGetSymbolAddress((void**)&kh, g_kh);  cudaGetSymbolAddress((void**)&kl, g_kl);
    cudaGetSymbolAddress((void**)&vt, g_vt);  cudaGetSymbolAddress((void**)&pp, g_p);

    static bool attrDone = false;
    if (!attrDone) {
        cudaFuncSetAttribute(proj_gemm<false, true>,
                             cudaFuncAttributeMaxDynamicSharedMemorySize, PSMEM);
        cudaFuncSetAttribute(proj_gemm<true, false>,
                             cudaFuncAttributeMaxDynamicSharedMemorySize, PSMEM);
        cudaFuncSetAttribute(gemm_h2_nt,
                             cudaFuncAttributeMaxDynamicSharedMemorySize, GSMEM);
        cudaFuncSetAttribute(gemm_h1_nt,
                             cudaFuncAttributeMaxDynamicSharedMemorySize, H1SMEM);
        attrDone = true;
    }

    // 1) projections: Q,K split fp16 (hi+lo); V single fp16, transposed
    {
        dim3 grd(EMB / 128, (BATCH * SEQ) / 128, 1);
        proj_gemm<false, true><<<grd, 512, PSMEM>>>(q_in, Wq, bq, qh, ql, EMB, EMB, EMB, EMB);
        proj_gemm<false, true><<<grd, 512, PSMEM>>>(k_in, Wk, bk, kh, kl, EMB, EMB, EMB, EMB);
        proj_gemm<true, false><<<grd, 512, PSMEM>>>(v_in, Wv, bv, vt, nullptr, EMB, EMB, EMB, SEQ);
    }

    // 2) scores[b] = q[b] @ k[b]^T  (fp16 x2 -> fp32)
    {
        dim3 grd(SEQ / 128, SEQ / 128, BATCH);
        gemm_h2_nt<<<grd, 512, GSMEM>>>(qh, ql, kh, kl, gs, EMB, EMB, EMB, SEQ,
                                        (long)SEQ * EMB, (long)SEQ * EMB,
                                        (long)SEQ * SEQ);
    }

    // 3) softmax -> single fp16 attn
    softmax_h<<<BATCH * SEQ, 256>>>(gs, pp);

    // 4) out[b] = attn[b] @ v[b]  (fp16 x1 -> fp32)
    {
        dim3 grd(EMB / 128, SEQ / 128, BATCH);
        gemm_h1_nt<<<grd, 512, H1SMEM>>>(pp, vt, out, SEQ, SEQ, SEQ, EMB,
                                         (long)SEQ * SEQ, (long)EMB * SEQ,
                                         (long)SEQ * EMB);
    }
}

// round 13
// speedup vs baseline: 1.4215x; 1.0287x over previous
#include <cuda_runtime.h>
#include <cuda_fp16.h>
#include <math.h>

#define BATCH 4
#define SEQ   4096
#define EMB   512

// Scratch (__device__ globals: sanctioned, no runtime allocation)
__device__ float g_s[(size_t)BATCH * SEQ * SEQ];                  // 256 MB scores
__device__ __half g_xqh[BATCH * SEQ * EMB], g_xql[BATCH * SEQ * EMB];
__device__ __half g_xkh[BATCH * SEQ * EMB], g_xkl[BATCH * SEQ * EMB];
__device__ __half g_xvh[BATCH * SEQ * EMB], g_xvl[BATCH * SEQ * EMB];
__device__ __half g_wqh[EMB * EMB], g_wql[EMB * EMB];
__device__ __half g_wkh[EMB * EMB], g_wkl[EMB * EMB];
__device__ __half g_wvh[EMB * EMB], g_wvl[EMB * EMB];
__device__ __half g_qh[BATCH * SEQ * EMB], g_ql[BATCH * SEQ * EMB];
__device__ __half g_kh[BATCH * SEQ * EMB], g_kl[BATCH * SEQ * EMB];
__device__ __half g_vt[BATCH * SEQ * EMB];                        // [b][e][s]
__device__ __half g_p [(size_t)BATCH * SEQ * SEQ];                // 128 MB attn

__device__ __forceinline__ unsigned packh(__half a, __half b) {
    return ((unsigned)__half_as_ushort(b) << 16) | __half_as_ushort(a);
}
__device__ __forceinline__ void cp16(unsigned dst, const void* src) {
    asm volatile("cp.async.cg.shared.global [%0], [%1], 16;" :: "r"(dst), "l"(src));
}

#define MMAH(aa, bb, mi, aj, bj)                                              \
    asm volatile(                                                             \
        "mma.sync.aligned.m16n8k16.row.col.f32.f16.f16.f32 "                  \
        "{%0,%1,%2,%3}, {%4,%5,%6,%7}, {%8,%9}, {%0,%1,%2,%3};"               \
        : "+f"(acc[mi][aj][0]), "+f"(acc[mi][aj][1]),                         \
          "+f"(acc[mi][aj][2]), "+f"(acc[mi][aj][3])                          \
        : "r"(aa[mi][0]), "r"(aa[mi][1]), "r"(aa[mi][2]), "r"(aa[mi][3]),     \
          "r"(bb[bj][0]), "r"(bb[bj][1]))

// ---------------------------------------------------------------------------
// Elementwise fp32 -> split fp16 (h = rn(x), l = rn(x - h)), float4-wide.
// ---------------------------------------------------------------------------
__global__ void __launch_bounds__(256)
split_f32(const float* __restrict__ src, __half* __restrict__ H,
          __half* __restrict__ L, int n4)
{
    const int stride = gridDim.x * blockDim.x;
    for (int i = blockIdx.x * blockDim.x + threadIdx.x; i < n4; i += stride) {
        float4 v = reinterpret_cast<const float4*>(src)[i];
        __half h0 = __float2half_rn(v.x), h1 = __float2half_rn(v.y);
        __half h2 = __float2half_rn(v.z), h3 = __float2half_rn(v.w);
        __half l0 = __float2half_rn(v.x - __half2float(h0));
        __half l1 = __float2half_rn(v.y - __half2float(h1));
        __half l2 = __float2half_rn(v.z - __half2float(h2));
        __half l3 = __float2half_rn(v.w - __half2float(h3));
        reinterpret_cast<uint2*>(H)[i] = make_uint2(packh(h0, h1), packh(h2, h3));
        reinterpret_cast<uint2*>(L)[i] = make_uint2(packh(l0, l1), packh(l2, l3));
    }
}

// ===========================================================================
// h2 GEMM core: acc += (Ah+Al)[m,k] * (Bh+Bl)[n,k] over K, CTA 128x128,
// BK=32, 512 threads (16 warps 4m x 4n), warp tile 32x32, cp.async double
// buffer, rows padded to 40 fp16 (80 B). __launch_bounds__(512,2) -> 2 CTA/SM.
// EPI: 0 = fp32 C (score), 1 = split fp16 + bias (Q/K proj),
//      2 = transposed single fp16 + bias (V proj).
// ===========================================================================
#define H2TILE_B  10240                      // 128 * 40 * 2 bytes
#define H2STAGE_B (4 * H2TILE_B)             // 40960
#define H2SMEM    (2 * H2STAGE_B)            // 81920 B -> 2 CTAs/SM

template <int EPI>
__global__ void __launch_bounds__(512, 2)
gemm_h2(const __half* __restrict__ Ah, const __half* __restrict__ Al,
        const __half* __restrict__ Bh, const __half* __restrict__ Bl,
        const float* __restrict__ bias,
        float* __restrict__ Cf, __half* __restrict__ Ch, __half* __restrict__ Cl,
        int K, int lda, int ldb, int ldc,
        long sA, long sB, long sC)
{
    extern __shared__ unsigned su[];

    const int bz = blockIdx.z;
    Ah += (long)bz * sA; Al += (long)bz * sA;
    Bh += (long)bz * sB; Bl += (long)bz * sB;

    const int tid  = threadIdx.x;
    const int lane = tid & 31;
    const int wid  = tid >> 5;
    const int wm   = (wid & 3) * 32;
    const int wn   = (wid >> 2) * 32;
    const int m0   = blockIdx.y * 128;
    const int n0   = blockIdx.x * 128;

    unsigned smemU;
    asm("{ .reg .u64 t; cvta.to.shared.u64 t, %1; cvt.u32.u64 %0, t; }"
        : "=r"(smemU) : "l"(su));

    const int crow = tid >> 2;               // 0..127
    const int cch  = tid & 3;                // chunk 0..3
    const unsigned dsto = (unsigned)(crow * 80 + cch * 16);

    auto stageCopy = [&](int buf, int kt) {
        const unsigned base = smemU + (unsigned)buf * H2STAGE_B;
        const long ao = (long)(m0 + crow) * lda + (long)kt * 32 + cch * 8;
        const long bo = (long)(n0 + crow) * ldb + (long)kt * 32 + cch * 8;
        cp16(base + 0 * H2TILE_B + dsto, Ah + ao);
        cp16(base + 1 * H2TILE_B + dsto, Bh + bo);
        cp16(base + 2 * H2TILE_B + dsto, Al + ao);
        cp16(base + 3 * H2TILE_B + dsto, Bl + bo);
    };

    float acc[2][4][4];
#pragma unroll
    for (int i = 0; i < 2; i++)
#pragma unroll
        for (int j = 0; j < 4; j++)
#pragma unroll
            for (int r = 0; r < 4; r++) acc[i][j][r] = 0.f;

    const int r8 = lane & 7;
    const int hb = (lane >> 3) & 1;
    const int hf = lane >> 4;
    unsigned aOff[2], bOff[2];
#pragma unroll
    for (int mi = 0; mi < 2; mi++)
        aOff[mi] = ((wm + mi * 16 + r8 + hb * 8) * 40 + hf * 8) * 2;
#pragma unroll
    for (int p = 0; p < 2; p++)
        bOff[p] = ((wn + p * 16 + r8 + hf * 8) * 40) * 2 + hb * 16;

    const int niter = K >> 5;

    stageCopy(0, 0);
    asm volatile("cp.async.commit_group;");

    for (int it = 0; it < niter; it++) {
        if (it + 1 < niter) {
            stageCopy((it + 1) & 1, it + 1);
            asm volatile("cp.async.commit_group;");
            asm volatile("cp.async.wait_group 1;");
        } else {
            asm volatile("cp.async.wait_group 0;");
        }
        __syncthreads();

        const unsigned stB = smemU + (unsigned)((it & 1) * H2STAGE_B);
        const unsigned aH = stB;
        const unsigned bH = stB + H2TILE_B;
        const unsigned aL = stB + 2u * H2TILE_B;
        const unsigned bL = stB + 3u * H2TILE_B;

#pragma unroll
        for (int ks = 0; ks < 2; ks++) {
            unsigned aFh[2][4], aFl[2][4];
            unsigned bFh[4][2], bFl[4][2];
#pragma unroll
            for (int mi = 0; mi < 2; mi++) {
                asm volatile("ldmatrix.sync.aligned.m8n8.x4.shared.b16 {%0,%1,%2,%3}, [%4];"
                    : "=r"(aFh[mi][0]), "=r"(aFh[mi][1]), "=r"(aFh[mi][2]), "=r"(aFh[mi][3])
                    : "r"(aH + aOff[mi] + ks * 32));
                asm volatile("ldmatrix.sync.aligned.m8n8.x4.shared.b16 {%0,%1,%2,%3}, [%4];"
                    : "=r"(aFl[mi][0]), "=r"(aFl[mi][1]), "=r"(aFl[mi][2]), "=r"(aFl[mi][3])
                    : "r"(aL + aOff[mi] + ks * 32));
            }
#pragma unroll
            for (int p = 0; p < 2; p++) {
                unsigned q0, q1, q2, q3;
                asm volatile("ldmatrix.sync.aligned.m8n8.x4.shared.b16 {%0,%1,%2,%3}, [%4];"
                    : "=r"(q0), "=r"(q1), "=r"(q2), "=r"(q3)
                    : "r"(bH + bOff[p] + ks * 32));
                bFh[2 * p][0] = q0; bFh[2 * p][1] = q1;
                bFh[2 * p + 1][0] = q2; bFh[2 * p + 1][1] = q3;
                asm volatile("ldmatrix.sync.aligned.m8n8.x4.shared.b16 {%0,%1,%2,%3}, [%4];"
                    : "=r"(q0), "=r"(q1), "=r"(q2), "=r"(q3)
                    : "r"(bL + bOff[p] + ks * 32));
                bFl[2 * p][0] = q0; bFl[2 * p][1] = q1;
                bFl[2 * p + 1][0] = q2; bFl[2 * p + 1][1] = q3;
            }
#pragma unroll
            for (int mi = 0; mi < 2; mi++)
#pragma unroll
                for (int nj = 0; nj < 4; nj++) {
                    MMAH(aFh, bFl, mi, nj, nj);
                    MMAH(aFl, bFh, mi, nj, nj);
                    MMAH(aFh, bFh, mi, nj, nj);
                }
        }
        __syncthreads();
    }

    // epilogue
    const int g = lane >> 2;
    const int t = lane & 3;
#pragma unroll
    for (int nj = 0; nj < 4; nj++) {
        const int col = n0 + wn + nj * 8 + t * 2;
        float b0 = 0.f, b1 = 0.f;
        if (EPI != 0) { b0 = bias[col]; b1 = bias[col + 1]; }
#pragma unroll
        for (int mi = 0; mi < 2; mi++) {
            const int row = m0 + wm + mi * 16 + g;
            float c0 = acc[mi][nj][0] + b0;
            float c1 = acc[mi][nj][1] + b1;
            float c2 = acc[mi][nj][2] + b0;
            float c3 = acc[mi][nj][3] + b1;
            if (EPI == 0) {
                float* Cp = Cf + (long)bz * sC;
                *reinterpret_cast<float2*>(&Cp[(long)row * ldc + col]) = make_float2(c0, c1);
                *reinterpret_cast<float2*>(&Cp[(long)(row + 8) * ldc + col]) = make_float2(c2, c3);
            } else if (EPI == 1) {
                __half h0 = __float2half_rn(c0), h1 = __float2half_rn(c1);
                __half h2 = __float2half_rn(c2), h3 = __float2half_rn(c3);
                __half l0 = __float2half_rn(c0 - __half2float(h0));
                __half l1 = __float2half_rn(c1 - __half2float(h1));
                __half l2 = __float2half_rn(c2 - __half2float(h2));
                __half l3 = __float2half_rn(c3 - __half2float(h3));
                *reinterpret_cast<unsigned*>(&Ch[(long)row * ldc + col])       = packh(h0, h1);
                *reinterpret_cast<unsigned*>(&Cl[(long)row * ldc + col])       = packh(l0, l1);
                *reinterpret_cast<unsigned*>(&Ch[(long)(row + 8) * ldc + col]) = packh(h2, h3);
                *reinterpret_cast<unsigned*>(&Cl[(long)(row + 8) * ldc + col]) = packh(l2, l3);
            } else {
                const int bb = row >> 12;
                const int s  = row & 4095;
                __half* Cp = Ch + (long)bb * EMB * SEQ + s;
                Cp[(long)col * SEQ]           = __float2half_rn(c0);
                Cp[(long)(col + 1) * SEQ]     = __float2half_rn(c1);
                Cp[(long)col * SEQ + 8]       = __float2half_rn(c2);
                Cp[(long)(col + 1) * SEQ + 8] = __float2half_rn(c3);
            }
        }
    }
}

// ===========================================================================
// AV GEMM x1 (single fp16 in, fp32 out) — validated round-11 kernel.
// BK=64, rows padded to 72, 73.7 KB smem -> 2 CTAs/SM.
// ===========================================================================
#define GTILE_B  18432
#define H1STAGE_B (2 * GTILE_B)
#define H1SMEM    (2 * H1STAGE_B)            // 73728 B

__global__ void __launch_bounds__(512)
gemm_h1_nt(const __half* __restrict__ A, const __half* __restrict__ B,
           float* __restrict__ C, int K, int lda, int ldb, int ldc,
           long sA, long sB, long sC)
{
    extern __shared__ unsigned su[];

    const int bz = blockIdx.z;
    A += (long)bz * sA;
    B += (long)bz * sB;
    C += (long)bz * sC;

    const int tid  = threadIdx.x;
    const int lane = tid & 31;
    const int wid  = tid >> 5;
    const int wm   = (wid & 3) * 32;
    const int wn   = (wid >> 2) * 32;
    const int m0   = blockIdx.y * 128;
    const int n0   = blockIdx.x * 128;

    unsigned smemU;
    asm("{ .reg .u64 t; cvta.to.shared.u64 t, %1; cvt.u32.u64 %0, t; }"
        : "=r"(smemU) : "l"(su));

    const int crow = tid >> 2;
    const int cc   = (tid & 3) * 8;
    const unsigned dsto = (unsigned)(crow * 144 + cc * 2);

    auto stageCopy = [&](int buf, int kt) {
        const unsigned base = smemU + (unsigned)buf * H1STAGE_B;
        const long ao = (long)(m0 + crow) * lda + (long)kt * 64 + cc;
        const long bo = (long)(n0 + crow) * ldb + (long)kt * 64 + cc;
        cp16(base + 0 * GTILE_B + dsto,      A + ao);
        cp16(base + 0 * GTILE_B + dsto + 64, A + ao + 32);
        cp16(base + 1 * GTILE_B + dsto,      B + bo);
        cp16(base + 1 * GTILE_B + dsto + 64, B + bo + 32);
    };

    float acc[2][4][4];
#pragma unroll
    for (int i = 0; i < 2; i++)
#pragma unroll
        for (int j = 0; j < 4; j++)
#pragma unroll
            for (int r = 0; r < 4; r++) acc[i][j][r] = 0.f;

    const int r8 = lane & 7;
    const int hb = (lane >> 3) & 1;
    const int hf = lane >> 4;
    unsigned aOff[2], bOff[2];
#pragma unroll
    for (int mi = 0; mi < 2; mi++)
        aOff[mi] = ((wm + mi * 16 + r8 + hb * 8) * 72 + hf * 8) * 2;
#pragma unroll
    for (int p = 0; p < 2; p++)
        bOff[p] = ((wn + p * 16 + r8 + hf * 8) * 72) * 2 + hb * 16;

    const int niter = K >> 6;

    stageCopy(0, 0);
    asm volatile("cp.async.commit_group;");

    for (int it = 0; it < niter; it++) {
        if (it + 1 < niter) {
            stageCopy((it + 1) & 1, it + 1);
            asm volatile("cp.async.commit_group;");
            asm volatile("cp.async.wait_group 1;");
        } else {
            asm volatile("cp.async.wait_group 0;");
        }
        __syncthreads();

        const unsigned stB = smemU + (unsigned)((it & 1) * H1STAGE_B);
        const unsigned aH = stB;
        const unsigned bH = stB + GTILE_B;

#pragma unroll
        for (int ks = 0; ks < 4; ks++) {
            unsigned aF[2][4];
            unsigned bF[4][2];
#pragma unroll
            for (int mi = 0; mi < 2; mi++) {
                asm volatile("ldmatrix.sync.aligned.m8n8.x4.shared.b16 {%0,%1,%2,%3}, [%4];"
                    : "=r"(aF[mi][0]), "=r"(aF[mi][1]), "=r"(aF[mi][2]), "=r"(aF[mi][3])
                    : "r"(aH + aOff[mi] + ks * 32));
            }
#pragma unroll
            for (int p = 0; p < 2; p++) {
                unsigned q0, q1, q2, q3;
                asm volatile("ldmatrix.sync.aligned.m8n8.x4.shared.b16 {%0,%1,%2,%3}, [%4];"
                    : "=r"(q0), "=r"(q1), "=r"(q2), "=r"(q3)
                    : "r"(bH + bOff[p] + ks * 32));
                bF[2 * p][0] = q0; bF[2 * p][1] = q1;
                bF[2 * p + 1][0] = q2; bF[2 * p + 1][1] = q3;
            }
#pragma unroll
            for (int mi = 0; mi < 2; mi++)
#pragma unroll
                for (int nj = 0; nj < 4; nj++)
                    MMAH(aF, bF, mi, nj, nj);
        }
        __syncthreads();
    }

    const int g = lane >> 2;
    const int t = lane & 3;
#pragma unroll
    for (int nj = 0; nj < 4; nj++) {
        const int col = n0 + wn + nj * 8 + t * 2;
#pragma unroll
        for (int mi = 0; mi < 2; mi++) {
            const int row = m0 + wm + mi * 16 + g;
            *reinterpret_cast<float2*>(&C[(long)row * ldc + col]) =
                make_float2(acc[mi][nj][0], acc[mi][nj][1]);
            *reinterpret_cast<float2*>(&C[(long)(row + 8) * ldc + col]) =
                make_float2(acc[mi][nj][2], acc[mi][nj][3]);
        }
    }
}

// ---------------------------------------------------------------------------
// Row softmax: fp32 scores -> single fp16 attn. 256 thr / 4096 cols.
// ---------------------------------------------------------------------------
__global__ void __launch_bounds__(256)
softmax_h(const float* __restrict__ S, __half* __restrict__ P)
{
    const long row = blockIdx.x;
    const float* p = S + row * (long)SEQ;
    const int tid  = threadIdx.x;
    const int lane = tid & 31;
    const int wid  = tid >> 5;

    float vals[16];
    float m = -3.0e38f;
#pragma unroll
    for (int i = 0; i < 4; i++) {
        float4 v = reinterpret_cast<const float4*>(p)[tid + i * 256];
        vals[i * 4 + 0] = v.x; vals[i * 4 + 1] = v.y;
        vals[i * 4 + 2] = v.z; vals[i * 4 + 3] = v.w;
        m = fmaxf(m, fmaxf(fmaxf(v.x, v.y), fmaxf(v.z, v.w)));
    }

    __shared__ float red[8];
#pragma unroll
    for (int off = 16; off > 0; off >>= 1)
        m = fmaxf(m, __shfl_xor_sync(0xffffffffu, m, off));
    if (lane == 0) red[wid] = m;
    __syncthreads();
    float mAll = red[0];
#pragma unroll
    for (int w = 1; w < 8; w++) mAll = fmaxf(mAll, red[w]);
    __syncthreads();

    float s = 0.f;
#pragma unroll
    for (int i = 0; i < 16; i++) {
        vals[i] = __expf(vals[i] - mAll);
        s += vals[i];
    }
#pragma unroll
    for (int off = 16; off > 0; off >>= 1)
        s += __shfl_xor_sync(0xffffffffu, s, off);
    if (lane == 0) red[wid] = s;
    __syncthreads();
    float sAll = 0.f;
#pragma unroll
    for (int w = 0; w < 8; w++) sAll += red[w];
    const float inv = 1.0f / sAll;

    uint2* ph = reinterpret_cast<uint2*>(P + row * (long)SEQ);
#pragma unroll
    for (int i = 0; i < 4; i++) {
        unsigned h0 = packh(__float2half_rn(vals[i * 4 + 0] * inv),
                            __float2half_rn(vals[i * 4 + 1] * inv));
        unsigned h1 = packh(__float2half_rn(vals[i * 4 + 2] * inv),
                            __float2half_rn(vals[i * 4 + 3] * inv));
        ph[tid + i * 256] = make_uint2(h0, h1);
    }
}

// ---------------------------------------------------------------------------
extern "C" void kernel_launch(void* const* d_in, const int* in_sizes, int n_in,
                              void* d_out, int out_size)
{
    const float* q_in = (const float*)d_in[0];
    const float* k_in = (const float*)d_in[1];
    const float* v_in = (const float*)d_in[2];
    const float* Wq   = (const float*)d_in[3];
    const float* bq   = (const float*)d_in[4];
    const float* Wk   = (const float*)d_in[5];
    const float* bk   = (const float*)d_in[6];
    const float* Wv   = (const float*)d_in[7];
    const float* bv   = (const float*)d_in[8];
    float* out = (float*)d_out;

    float* gs;
    __half *xqh, *xql, *xkh, *xkl, *xvh, *xvl;
    __half *wqh, *wql, *wkh, *wkl, *wvh, *wvl;
    __half *qh, *ql, *kh, *kl, *vt, *pp;
    cudaGetSymbolAddress((void**)&gs, g_s);
    cudaGetSymbolAddress((void**)&xqh, g_xqh); cudaGetSymbolAddress((void**)&xql, g_xql);
    cudaGetSymbolAddress((void**)&xkh, g_xkh); cudaGetSymbolAddress((void**)&xkl, g_xkl);
    cudaGetSymbolAddress((void**)&xvh, g_xvh); cudaGetSymbolAddress((void**)&xvl, g_xvl);
    cudaGetSymbolAddress((void**)&wqh, g_wqh); cudaGetSymbolAddress((void**)&wql, g_wql);
    cudaGetSymbolAddress((void**)&wkh, g_wkh); cudaGetSymbolAddress((void**)&wkl, g_wkl);
    cudaGetSymbolAddress((void**)&wvh, g_wvh); cudaGetSymbolAddress((void**)&wvl, g_wvl);
    cudaGetSymbolAddress((void**)&qh, g_qh);   cudaGetSymbolAddress((void**)&ql, g_ql);
    cudaGetSymbolAddress((void**)&kh, g_kh);   cudaGetSymbolAddress((void**)&kl, g_kl);
    cudaGetSymbolAddress((void**)&vt, g_vt);   cudaGetSymbolAddress((void**)&pp, g_p);

    static bool attrDone = false;
    if (!attrDone) {
        cudaFuncSetAttribute(gemm_h2<0>, cudaFuncAttributeMaxDynamicSharedMemorySize, H2SMEM);
        cudaFuncSetAttribute(gemm_h2<1>, cudaFuncAttributeMaxDynamicSharedMemorySize, H2SMEM);
        cudaFuncSetAttribute(gemm_h2<2>, cudaFuncAttributeMaxDynamicSharedMemorySize, H2SMEM);
        cudaFuncSetAttribute(gemm_h1_nt, cudaFuncAttributeMaxDynamicSharedMemorySize, H1SMEM);
        attrDone = true;
    }

    const int NX4 = BATCH * SEQ * EMB / 4;   // 2M float4
    const int NW4 = EMB * EMB / 4;           // 64K float4

    // 0) pre-split inputs & weights to fp16 h/l
    split_f32<<<2048, 256>>>(q_in, xqh, xql, NX4);
    split_f32<<<2048, 256>>>(k_in, xkh, xkl, NX4);
    split_f32<<<2048, 256>>>(v_in, xvh, xvl, NX4);
    split_f32<<<256, 256>>>(Wq, wqh, wql, NW4);
    split_f32<<<256, 256>>>(Wk, wkh, wkl, NW4);
    split_f32<<<256, 256>>>(Wv, wvh, wvl, NW4);

    // 1) projections (h2, pre-split): Q,K split-out; V transposed single-out
    {
        dim3 grd(EMB / 128, (BATCH * SEQ) / 128, 1);
        gemm_h2<1><<<grd, 512, H2SMEM>>>(xqh, xql, wqh, wql, bq,
                                         nullptr, qh, ql, EMB, EMB, EMB, EMB, 0, 0, 0);
        gemm_h2<1><<<grd, 512, H2SMEM>>>(xkh, xkl, wkh, wkl, bk,
                                         nullptr, kh, kl, EMB, EMB, EMB, EMB, 0, 0, 0);
        gemm_h2<2><<<grd, 512, H2SMEM>>>(xvh, xvl, wvh, wvl, bv,
                                         nullptr, vt, nullptr, EMB, EMB, EMB, SEQ, 0, 0, 0);
    }

    // 2) scores[b] = q[b] @ k[b]^T  (h2, fp32 out)
    {
        dim3 grd(SEQ / 128, SEQ / 128, BATCH);
        gemm_h2<0><<<grd, 512, H2SMEM>>>(qh, ql, kh, kl, nullptr,
                                         gs, nullptr, nullptr, EMB, EMB, EMB, SEQ,
                                         (long)SEQ * EMB, (long)SEQ * EMB,
                                         (long)SEQ * SEQ);
    }

    // 3) softmax -> single fp16 attn
    softmax_h<<<BATCH * SEQ, 256>>>(gs, pp);

    // 4) out[b] = attn[b] @ v[b]  (h1)
    {
        dim3 grd(EMB / 128, SEQ / 128, BATCH);
        gemm_h1_nt<<<grd, 512, H1SMEM>>>(pp, vt, out, SEQ, SEQ, SEQ, EMB,
                                         (long)SEQ * SEQ, (long)EMB * SEQ,
                                         (long)SEQ * EMB);
    }
}